// round 12
// baseline (speedup 1.0000x reference)
#include <cuda_runtime.h>
#include <math.h>

#define DD 256
#define HH 512
#define BB 128
typedef unsigned long long ull;

__device__ __forceinline__ ull packf2(float lo, float hi) {
    return ((ull)__float_as_uint(hi) << 32) | (ull)__float_as_uint(lo);
}
__device__ __forceinline__ float lof(ull v) { return __uint_as_float((unsigned)v); }
__device__ __forceinline__ float hif(ull v) { return __uint_as_float((unsigned)(v >> 32)); }
__device__ __forceinline__ void ffma2(ull& d, ull a, ull b) {
    asm("fma.rn.f32x2 %0, %1, %2, %0;" : "+l"(d) : "l"(a), "l"(b));
}
#define BAR_SYNC(id)   asm volatile("bar.sync %0, 544;"   :: "r"(id) : "memory")
#define BAR_ARRIVE(id) asm volatile("bar.arrive %0, 544;" :: "r"(id) : "memory")
#define BPAR0 1   // ids 1..4: par(step) ready, step&3
#define BPUB0 5   // ids 5..8: pub(step) ready, step&3

// Wide weights (UNCHANGED layout from the 107us kernel)
__device__ ulonglong2 g_wA[260 * 512];  // row j: (w0[u][j-1] mu,lv), (W1[u][S(j-1)s0] mu,lv)
__device__ ull g_wA2[260 * 512];        // row j: (W1[u][S(j-1)s1] mu,lv)
__device__ ull g_wO[260 * 512];         // row j: (Wo[ocol][S(j-1)s0], Wo[ocol][S(j-1)s1])
__device__ ull g_w3p[2 * 512];          // S(1)/S(2) slot2 W1
__device__ float g_w3o[2 * 512];        // S(1)/S(2) slot2 Wo
// Combiner records, 2-deep-history layout
__device__ float g_recS[256 * 56];      // steady (i>=6)
__device__ float g_recW[6 * 100];       // warm (i<6), 3-slot capacity

__device__ __forceinline__ int permf(int p) {
    if (p < 3) return (p == 0) ? 0 : ((p == 1) ? 255 : 510);
    if (p < 6) { int q = p - 3; return (q == 0) ? 1 : ((q == 1) ? 256 : 511); }
    int d = 3 + ((p - 6) >> 1);
    return (((p - 6) & 1) == 0) ? (d - 1) : (d + 254);
}
__device__ __forceinline__ int degf(int p) {
    if (p < 3) return 1;
    if (p < 6) return 2;
    return 3 + ((p - 6) >> 1);
}
__device__ __forceinline__ int Pof(int k) {
    if (k <= 0) return 0;
    if (k == 1) return 3;
    int v = 2 * k + 2;
    return v > HH ? HH : v;
}
__device__ __forceinline__ int ccf(int d) {   // |S(d)|
    if (d <= 0) return 0;
    return (d <= 2) ? 3 : (d <= 255 ? 2 : 0);
}
__device__ __forceinline__ float elu1(float a) {
    float e = __expf(a) - 1.f;
    return a > 0.f ? a : e;
}

__global__ void setup_kernel(
    const float* __restrict__ W0m, const float* __restrict__ W1m, const float* __restrict__ Wom,
    const float* __restrict__ b0m, const float* __restrict__ b1m,
    const float* __restrict__ W0l, const float* __restrict__ W1l, const float* __restrict__ Wol,
    const float* __restrict__ b0l, const float* __restrict__ b1l,
    const float* __restrict__ bom, const float* __restrict__ bol)
{
    int tid = blockIdx.x * blockDim.x + threadIdx.x;
    int stride = gridDim.x * blockDim.x;

    // ---- wide arrays (unchanged) ----
    for (int idx = tid; idx < 256 * 512; idx += stride) {
        int i = idx >> 9, u = idx & 511;
        int du = degf(u), ou = permf(u);
        int onet = u >> 8, ocol = u & 255;
        const float* Wo = onet ? Wol : Wom;

        int w0row = i - 1 < 0 ? 0 : i - 1;
        float m0 = (du >= w0row + 1) ? 1.f : 0.f;
        float w0mu = m0 * W0m[ou * DD + w0row];
        float w0lv = m0 * W0l[ou * DD + w0row];

        int pB = Pof(i - 2);
        float w1s[2][2], wos[2];
#pragma unroll
        for (int s = 0; s < 2; s++) {
            int p = pB + s; if (p > HH - 1) p = HH - 1;
            int op = permf(p), dp = degf(p);
            float m1 = (du >= dp) ? 1.f : 0.f;
            w1s[s][0] = m1 * W1m[ou * HH + op];
            w1s[s][1] = m1 * W1l[ou * HH + op];
            float mo = (ocol >= dp) ? 1.f : 0.f;
            wos[s] = mo * Wo[ocol * HH + op];
        }
        g_wA[i * 512 + u] = make_ulonglong2(packf2(w0mu, w0lv), packf2(w1s[0][0], w1s[0][1]));
        g_wA2[i * 512 + u] = packf2(w1s[1][0], w1s[1][1]);
        g_wO[i * 512 + u] = packf2(wos[0], wos[1]);
    }
    for (int idx = tid; idx < 1024; idx += stride) {
        int j = idx >> 9, u = idx & 511;
        int du = degf(u), ou = permf(u);
        int onet = u >> 8, ocol = u & 255;
        const float* Wo = onet ? Wol : Wom;
        int p = (j == 0) ? 2 : 5;
        int op = permf(p), dp = degf(p);
        float m1 = (du >= dp) ? 1.f : 0.f;
        float mo = (ocol >= dp) ? 1.f : 0.f;
        g_w3p[idx] = packf2(m1 * W1m[ou * HH + op], m1 * W1l[ou * HH + op]);
        g_w3o[idx] = mo * Wo[ocol * HH + op];
    }

    // ---- steady records (i>=6 used; 2 slots everywhere) ----
    for (int i = tid; i < 256; i += stride) {
        float* r = g_recS + i * 56;
        for (int k = 0; k < 56; k++) r[k] = 0.f;
        if (i >= 6) {
            int cB = Pof(i - 1), b1B = Pof(i - 2), b2B = Pof(i - 3);
            for (int s = 0; s < 2; s++) {
                int u = permf(cB + s);
                r[0 + 2 * s]  = W0m[u * DD + (i - 2)]; r[1 + 2 * s]  = W0l[u * DD + (i - 2)];
                r[4 + 2 * s]  = W0m[u * DD + (i - 1)]; r[5 + 2 * s]  = W0l[u * DD + (i - 1)];
                r[8 + 2 * s]  = b0m[u];                r[9 + 2 * s]  = b0l[u];
                r[12 + 2 * s] = b1m[u];                r[13 + 2 * s] = b1l[u];
                r[48 + 2 * s] = Wom[i * HH + u];       r[49 + 2 * s] = Wol[i * HH + u];
            }
            for (int sp = 0; sp < 2; sp++) {
                int p2 = permf(b2B + sp), p1 = permf(b1B + sp), pc = permf(cB + sp);
                r[40 + 2 * sp] = Wom[i * HH + p2]; r[41 + 2 * sp] = Wol[i * HH + p2];
                r[44 + 2 * sp] = Wom[i * HH + p1]; r[45 + 2 * sp] = Wol[i * HH + p1];
                for (int sc = 0; sc < 2; sc++) {
                    int g = permf(cB + sc);
                    r[16 + sp * 4 + 2 * sc] = W1m[g * HH + p2];
                    r[17 + sp * 4 + 2 * sc] = W1l[g * HH + p2];
                    r[24 + sp * 4 + 2 * sc] = W1m[g * HH + p1];
                    r[25 + sp * 4 + 2 * sc] = W1l[g * HH + p1];
                    r[32 + sp * 4 + 2 * sc] = W1m[g * HH + pc];
                    r[33 + sp * 4 + 2 * sc] = W1l[g * HH + pc];
                }
            }
            r[52] = bom[i]; r[53] = bol[i];
        }
    }
    // ---- warm records (i<6, 3-slot capacity) ----
    for (int i = tid; i < 6; i += stride) {
        float* rw = g_recW + i * 100;
        for (int k = 0; k < 100; k++) rw[k] = 0.f;
        int cc = ccf(i), c1 = ccf(i - 1), c2 = ccf(i - 2);
        int cB = Pof(i - 1), b1B = Pof(i - 2), b2B = Pof(i - 3);
        for (int s = 0; s < cc; s++) {
            int u = permf(cB + s);
            if (i >= 2) { rw[0 + 2 * s] = W0m[u * DD + (i - 2)]; rw[1 + 2 * s] = W0l[u * DD + (i - 2)]; }
            if (i >= 1) { rw[6 + 2 * s] = W0m[u * DD + (i - 1)]; rw[7 + 2 * s] = W0l[u * DD + (i - 1)]; }
            rw[12 + 2 * s] = b0m[u]; rw[13 + 2 * s] = b0l[u];
            rw[18 + 2 * s] = b1m[u]; rw[19 + 2 * s] = b1l[u];
            rw[90 + 2 * s] = Wom[i * HH + u]; rw[91 + 2 * s] = Wol[i * HH + u];
        }
        for (int sp = 0; sp < c2; sp++) {
            int p2 = permf(b2B + sp);
            rw[78 + 2 * sp] = Wom[i * HH + p2]; rw[79 + 2 * sp] = Wol[i * HH + p2];
            for (int sc = 0; sc < cc; sc++) {
                int g = permf(cB + sc);
                rw[24 + sp * 6 + 2 * sc] = W1m[g * HH + p2];
                rw[25 + sp * 6 + 2 * sc] = W1l[g * HH + p2];
            }
        }
        for (int sp = 0; sp < c1; sp++) {
            int p1 = permf(b1B + sp);
            rw[84 + 2 * sp] = Wom[i * HH + p1]; rw[85 + 2 * sp] = Wol[i * HH + p1];
            for (int sc = 0; sc < cc; sc++) {
                int g = permf(cB + sc);
                rw[42 + sp * 6 + 2 * sc] = W1m[g * HH + p1];
                rw[43 + sp * 6 + 2 * sc] = W1l[g * HH + p1];
            }
        }
        for (int sp = 0; sp < cc; sp++) {
            int pc = permf(cB + sp);
            for (int sc = 0; sc < cc; sc++) {
                int g = permf(cB + sc);
                rw[60 + sp * 6 + 2 * sc] = W1m[g * HH + pc];
                rw[61 + sp * 6 + 2 * sc] = W1l[g * HH + pc];
            }
        }
        rw[96] = bom[i]; rw[97] = bol[i];
    }
}

// dynamic smem layout (float indices)
#define OFF_RECS 0                  // 256*56 = 14336
#define OFF_RECW 14336              // 600
#define OFF_XS   14936              // 256
#define OFF_PUB  15192              // 4*16
#define OFF_PAR  15256              // 4*16
#define SM_FLOATS 15320
#define SMEM_BYTES (SM_FLOATS * 4)

struct H2 { float v[2][2]; };  // [slot][net]

// steady comb: 2 current slots; histories A = step i-1, B = step i-2
__device__ __forceinline__ void comb_step_steady(
    const float* __restrict__ par, float* __restrict__ pub,
    const float rr[56], float xi,
    float& nc1, float& nc2,
    H2& h0A, H2& h0B, H2& h1A, H2& h1B,
    float& lvsum, float* __restrict__ outp, bool lead)
{
    float pp[16];
#pragma unroll
    for (int k = 0; k < 4; k++) *(float4*)(pp + 4 * k) = *(const float4*)(par + 4 * k);
    float h0c[2][2], h1c[2][2];
#pragma unroll
    for (int s = 0; s < 2; s++)
#pragma unroll
        for (int n = 0; n < 2; n++)
            h0c[s][n] = elu1(pp[4 * s + n] + nc2 * rr[2 * s + n]
                             + nc1 * rr[4 + 2 * s + n] + rr[8 + 2 * s + n]);
#pragma unroll
    for (int sc = 0; sc < 2; sc++)
#pragma unroll
        for (int n = 0; n < 2; n++) {
            float a = pp[4 * sc + 2 + n] + rr[12 + 2 * sc + n];
#pragma unroll
            for (int sp = 0; sp < 2; sp++) a = fmaf(h0B.v[sp][n], rr[16 + sp * 4 + 2 * sc + n], a);
#pragma unroll
            for (int sp = 0; sp < 2; sp++) a = fmaf(h0A.v[sp][n], rr[24 + sp * 4 + 2 * sc + n], a);
#pragma unroll
            for (int sp = 0; sp < 2; sp++) a = fmaf(h0c[sp][n], rr[32 + sp * 4 + 2 * sc + n], a);
            h1c[sc][n] = elu1(a);
        }
    float mu = pp[12] + rr[52];
    float lv = pp[13] + rr[53];
#pragma unroll
    for (int sp = 0; sp < 2; sp++) {
        mu = fmaf(h1B.v[sp][0], rr[40 + 2 * sp], mu); lv = fmaf(h1B.v[sp][1], rr[41 + 2 * sp], lv);
        mu = fmaf(h1A.v[sp][0], rr[44 + 2 * sp], mu); lv = fmaf(h1A.v[sp][1], rr[45 + 2 * sp], lv);
        mu = fmaf(h1c[sp][0],   rr[48 + 2 * sp], mu); lv = fmaf(h1c[sp][1],   rr[49 + 2 * sp], lv);
    }
    const float ls = 0.5f * lv;
    const float nc = (xi - mu) * __expf(-ls);
    lvsum += ls;
    if (lead) {
        *outp = nc;
        *(ull*)(pub + 0) = packf2(nc, nc);
        *(ull*)(pub + 2) = packf2(h0c[0][0], h0c[0][1]);
        *(ull*)(pub + 4) = packf2(h0c[1][0], h0c[1][1]);
        *(ull*)(pub + 6) = packf2(h1c[0][0], h1c[1][0]);
        *(ull*)(pub + 8) = packf2(h1c[0][1], h1c[1][1]);
    }
    nc2 = nc1; nc1 = nc;
#pragma unroll
    for (int s = 0; s < 2; s++)
#pragma unroll
        for (int n = 0; n < 2; n++) {
            h0B.v[s][n] = h0A.v[s][n]; h0A.v[s][n] = h0c[s][n];
            h1B.v[s][n] = h1A.v[s][n]; h1A.v[s][n] = h1c[s][n];
        }
}

// warm comb: 3-slot capacity, array histories
__device__ __forceinline__ void comb_step_warm(
    const float* __restrict__ par, float* __restrict__ pub,
    const float* __restrict__ rw, float xi,
    float& nc1, float& nc2,
    float h0A[3][2], float h0B[3][2], float h1A[3][2], float h1B[3][2],
    float& lvsum, float* __restrict__ outp, bool lead)
{
    float pp[16];
#pragma unroll
    for (int k = 0; k < 4; k++) *(float4*)(pp + 4 * k) = *(const float4*)(par + 4 * k);
    float h0c[3][2], h1c[3][2];
#pragma unroll
    for (int s = 0; s < 3; s++)
#pragma unroll
        for (int n = 0; n < 2; n++) {
            float pa0 = (s < 2) ? pp[4 * s + n] : pp[8 + n];
            h0c[s][n] = elu1(pa0 + nc2 * rw[2 * s + n]
                             + nc1 * rw[6 + 2 * s + n] + rw[12 + 2 * s + n]);
        }
#pragma unroll
    for (int sc = 0; sc < 3; sc++)
#pragma unroll
        for (int n = 0; n < 2; n++) {
            float a = ((sc < 2) ? pp[4 * sc + 2 + n] : pp[10 + n]) + rw[18 + 2 * sc + n];
#pragma unroll
            for (int sp = 0; sp < 3; sp++) a = fmaf(h0B[sp][n], rw[24 + sp * 6 + 2 * sc + n], a);
#pragma unroll
            for (int sp = 0; sp < 3; sp++) a = fmaf(h0A[sp][n], rw[42 + sp * 6 + 2 * sc + n], a);
#pragma unroll
            for (int sp = 0; sp < 3; sp++) a = fmaf(h0c[sp][n], rw[60 + sp * 6 + 2 * sc + n], a);
            h1c[sc][n] = elu1(a);
        }
    float mu = pp[12] + rw[96];
    float lv = pp[13] + rw[97];
#pragma unroll
    for (int sp = 0; sp < 3; sp++) {
        mu = fmaf(h1B[sp][0], rw[78 + 2 * sp], mu); lv = fmaf(h1B[sp][1], rw[79 + 2 * sp], lv);
        mu = fmaf(h1A[sp][0], rw[84 + 2 * sp], mu); lv = fmaf(h1A[sp][1], rw[85 + 2 * sp], lv);
        mu = fmaf(h1c[sp][0], rw[90 + 2 * sp], mu); lv = fmaf(h1c[sp][1], rw[91 + 2 * sp], lv);
    }
    const float ls = 0.5f * lv;
    const float nc = (xi - mu) * __expf(-ls);
    lvsum += ls;
    if (lead) {
        *outp = nc;
        *(ull*)(pub + 0)  = packf2(nc, nc);
        *(ull*)(pub + 2)  = packf2(h0c[0][0], h0c[0][1]);
        *(ull*)(pub + 4)  = packf2(h0c[1][0], h0c[1][1]);
        *(ull*)(pub + 6)  = packf2(h1c[0][0], h1c[1][0]);
        *(ull*)(pub + 8)  = packf2(h1c[0][1], h1c[1][1]);
        *(ull*)(pub + 10) = packf2(h0c[2][0], h0c[2][1]);
        *(ull*)(pub + 12) = packf2(h1c[2][0], h1c[2][1]);
    }
    nc2 = nc1; nc1 = nc;
#pragma unroll
    for (int s = 0; s < 3; s++)
#pragma unroll
        for (int n = 0; n < 2; n++) {
            h0B[s][n] = h0A[s][n]; h0A[s][n] = h0c[s][n];
            h1B[s][n] = h1A[s][n]; h1A[s][n] = h1c[s][n];
        }
}

// wide sub-step body (consumes pub(j-1), publishes par(j+2))
__device__ __forceinline__ void wide_body(
    int j, const float* __restrict__ pb, int onet,
    ulonglong2 Wa, ull Wa2, ull Wo,
    ull& A0, ull& A1, ull& AO, float& aoutC,
    int pubA2, int pubO2, float* __restrict__ parw, int off,
    ull w3p2, ull w3p3, float w3o2, float w3o3)
{
    if (j <= pubA2) {
        const ull nc2v = *(const ull*)(pb + 0);
        const ull h0s0 = *(const ull*)(pb + 2);
        const ull h0s1 = *(const ull*)(pb + 4);
        ffma2(A0, nc2v, Wa.x);
        ffma2(A1, h0s0, Wa.y);
        ffma2(A1, h0s1, Wa2);
        if ((unsigned)(j - 2) < 2u) {
            const ull h0s2 = *(const ull*)(pb + 10);
            ffma2(A1, h0s2, (j == 2) ? w3p2 : w3p3);
        }
        if (j == pubA2) { *(ull*)(parw + off) = A0; *(ull*)(parw + off + 2) = A1; }
    }
    if (j <= pubO2) {
        const ull h1p = *(const ull*)(pb + 6 + 2 * onet);
        ffma2(AO, h1p, Wo);
        if ((unsigned)(j - 2) < 2u)
            aoutC = fmaf(pb[12 + onet], (j == 2) ? w3o2 : w3o3, aoutC);
        if (j == pubO2) parw[12 + onet] = lof(AO) + hif(AO) + aoutC;
    }
}

// 128 CTAs, 544 threads. tid<512: wide; warp 16: combiner (lane tid==512 leads).
__global__ __launch_bounds__(544, 1) void made_kernel(
    const float* __restrict__ x, float* __restrict__ out)
{
    extern __shared__ __align__(16) float SM[];

    const int tid = threadIdx.x;
    const int b = blockIdx.x;

    {
        const float4* srcS = (const float4*)g_recS;
        float4* dstS = (float4*)(SM + OFF_RECS);
        for (int k = tid; k < (256 * 56) / 4; k += 544) dstS[k] = srcS[k];
        const float4* srcW = (const float4*)g_recW;
        float4* dstW = (float4*)(SM + OFF_RECW);
        for (int k = tid; k < 600 / 4; k += 544) dstW[k] = srcW[k];
        if (tid < 256) SM[OFF_XS + tid] = x[b * DD + tid];
        for (int k = tid; k < 128; k += 544) SM[OFF_PUB + k] = 0.f;
    }
    __syncthreads();

    float* const pubB = SM + OFF_PUB;
    float* const parB = SM + OFF_PAR;
    float* const outb = out + b * DD;

    if (tid < 512) {
        // ================= WIDE =================
        const int u = tid;
        const int du = degf(u);
        const int su = u - Pof(du - 1);
        const int onet = (tid >> 8) & 1;
        const int ocol = tid & 255;
        const int pubA2 = du - 2;
        const int pubO2 = ocol - 2;
        const int off = (su < 2) ? (su << 2) : 8;

        ull A0 = 0, A1 = 0, AO = 0;
        float aoutC = 0.f;

        const ulonglong2* wA = g_wA + u;
        const ull* wA2 = g_wA2 + u;
        const ull* wO = g_wO + u;
        ulonglong2 WaE = wA[0],   WaO = wA[512];
        ull Wa2E = wA2[0], Wa2O = wA2[512];
        ull WoE = wO[0],   WoO = wO[512];
        const ull w3p2 = g_w3p[u], w3p3 = g_w3p[512 + u];
        const float w3o2 = g_w3o[u], w3o3 = g_w3o[512 + u];

        BAR_ARRIVE(BPAR0 + 0);   // prime par(0) = zeros
        BAR_ARRIVE(BPAR0 + 1);   // prime par(1) = zeros

#pragma unroll 1
        for (int j = 0; j < 254; j += 2) {
            // even j
            {
                const int ip = (j + 3) & 3;          // (j-1)&3
                const int ia = (j + 2) & 3;
                BAR_SYNC(BPUB0 + ip);
                wide_body(j, pubB + (ip << 4), onet, WaE, Wa2E, WoE,
                          A0, A1, AO, aoutC, pubA2, pubO2,
                          parB + (ia << 4), off, w3p2, w3p3, w3o2, w3o3);
                __threadfence_block();
                BAR_ARRIVE(BPAR0 + ia);
                if (j + 2 <= pubA2) { WaE = wA[(j + 2) << 9]; Wa2E = wA2[(j + 2) << 9]; }
                if (j + 2 <= pubO2) { WoE = wO[(j + 2) << 9]; }
            }
            // odd j+1
            {
                const int ip = j & 3;                // ((j+1)-1)&3
                const int ia = (j + 3) & 3;
                BAR_SYNC(BPUB0 + ip);
                wide_body(j + 1, pubB + (ip << 4), onet, WaO, Wa2O, WoO,
                          A0, A1, AO, aoutC, pubA2, pubO2,
                          parB + (ia << 4), off, w3p2, w3p3, w3o2, w3o3);
                __threadfence_block();
                BAR_ARRIVE(BPAR0 + ia);
                if (j + 3 <= pubA2) { WaO = wA[(j + 3) << 9]; Wa2O = wA2[(j + 3) << 9]; }
                if (j + 3 <= pubO2) { WoO = wO[(j + 3) << 9]; }
            }
        }
    } else {
        // ================= COMBINER (warp 16) =================
        const bool lead = (tid == 512);
        float nc1 = 0.f, nc2 = 0.f, lvsum = 0.f;
        float h0Aw[3][2] = {}, h0Bw[3][2] = {}, h1Aw[3][2] = {}, h1Bw[3][2] = {};

        BAR_ARRIVE(BPUB0 + 3);   // prime pub(-1) = zeros

        // warm steps 0..5
#pragma unroll 1
        for (int i = 0; i < 6; i++) {
            const int idx = i & 3;
            BAR_SYNC(BPAR0 + idx);
            comb_step_warm(parB + (idx << 4), pubB + (idx << 4),
                           SM + OFF_RECW + i * 100, SM[OFF_XS + i],
                           nc1, nc2, h0Aw, h0Bw, h1Aw, h1Bw,
                           lvsum, outb + i, lead);
            __threadfence_block();
            BAR_ARRIVE(BPUB0 + idx);
        }
        // handoff to 2-slot steady state
        H2 h0A, h0B, h1A, h1B;
#pragma unroll
        for (int s = 0; s < 2; s++)
#pragma unroll
            for (int n = 0; n < 2; n++) {
                h0A.v[s][n] = h0Aw[s][n]; h0B.v[s][n] = h0Bw[s][n];
                h1A.v[s][n] = h1Aw[s][n]; h1B.v[s][n] = h1Bw[s][n];
            }
        // preload record for i = 6
        float rr[56];
#pragma unroll
        for (int k = 0; k < 14; k++)
            *(float4*)(rr + 4 * k) = *(const float4*)(SM + OFF_RECS + 6 * 56 + 4 * k);
        float xiN = SM[OFF_XS + 6];

#pragma unroll 1
        for (int i = 6; i < 256; i++) {
            const int idx = i & 3;
            BAR_SYNC(BPAR0 + idx);
            comb_step_steady(parB + (idx << 4), pubB + (idx << 4), rr, xiN,
                             nc1, nc2, h0A, h0B, h1A, h1B,
                             lvsum, outb + i, lead);
            __threadfence_block();
            BAR_ARRIVE(BPUB0 + idx);
            if (i + 1 < 256) {
                const float* rp = SM + OFF_RECS + (i + 1) * 56;
#pragma unroll
                for (int k = 0; k < 14; k++)
                    *(float4*)(rr + 4 * k) = *(const float4*)(rp + 4 * k);
                xiN = SM[OFF_XS + i + 1];
            }
        }
        if (lead) out[BB * DD + b] = lvsum;
    }
}

extern "C" void kernel_launch(void* const* d_in, const int* in_sizes, int n_in,
                              void* d_out, int out_size) {
    const float* xx   = (const float*)d_in[0];
    const float* muW0 = (const float*)d_in[1];
    const float* mub0 = (const float*)d_in[2];
    const float* muW1 = (const float*)d_in[3];
    const float* mub1 = (const float*)d_in[4];
    const float* muWo = (const float*)d_in[5];
    const float* mubo = (const float*)d_in[6];
    const float* lvW0 = (const float*)d_in[7];
    const float* lvb0 = (const float*)d_in[8];
    const float* lvW1 = (const float*)d_in[9];
    const float* lvb1 = (const float*)d_in[10];
    const float* lvWo = (const float*)d_in[11];
    const float* lvbo = (const float*)d_in[12];
    float* out = (float*)d_out;

    cudaFuncSetAttribute(made_kernel, cudaFuncAttributeMaxDynamicSharedMemorySize, SMEM_BYTES);
    setup_kernel<<<512, 256>>>(muW0, muW1, muWo, mub0, mub1,
                               lvW0, lvW1, lvWo, lvb0, lvb1, mubo, lvbo);
    made_kernel<<<BB, 544, SMEM_BYTES>>>(xx, out);
}